// round 3
// baseline (speedup 1.0000x reference)
#include <cuda_runtime.h>
#include <math.h>

#define NB 8
#define NC 256
#define HD 128
#define HW (HD*HD)
#define HM 512

// scratch (allocation-free rule: __device__ globals)
__device__ __align__(16) float g_m[NB*HW];     // resized mask
__device__ __align__(16) float g_avg[NB*HW];   // m * mean_c(x)
__device__ __align__(16) float g_maxp[NB*HW];  // m * max_c(x)
__device__ __align__(16) float g_s[NB*HW];     // m * sigmoid(conv)

// ---------------------------------------------------------------------------
// m(b, r, q): antialiased bilinear 512->128 (half-pixel, antialias triangle).
// 8 taps/dim, weights {1,3,5,7,7,5,3,1}/8, renormalized at edges.
// ---------------------------------------------------------------------------
__device__ __forceinline__ float resize_m(const float* __restrict__ mp, int r, int q) {
    const float raw[8] = {0.125f,0.375f,0.625f,0.875f,0.875f,0.625f,0.375f,0.125f};
    float wr[8], wc[8]; int jr[8], jc[8];
    float tr = 0.f, tc = 0.f;
#pragma unroll
    for (int k = 0; k < 8; k++) {
        int j = 4*r - 2 + k;
        bool ok = (j >= 0) && (j < HM);
        wr[k] = ok ? raw[k] : 0.f;
        jr[k] = ok ? j : 0;
        tr += wr[k];
        j = 4*q - 2 + k;
        ok = (j >= 0) && (j < HM);
        wc[k] = ok ? raw[k] : 0.f;
        jc[k] = ok ? j : 0;
        tc += wc[k];
    }
    float acc = 0.f;
#pragma unroll
    for (int a = 0; a < 8; a++) {
        float rowacc = 0.f;
#pragma unroll
        for (int bb = 0; bb < 8; bb++)
            rowacc += wc[bb] * __ldg(mp + jr[a]*HM + jc[bb]);
        acc += wr[a] * rowacc;
    }
    return acc / (tr * tc);
}

// ---------------------------------------------------------------------------
// Kernel B (fused resize+chanstat): per pixel pair: compute m inline (hidden
// under the 256-channel load latency), mean/max over channels, premultiply.
// ---------------------------------------------------------------------------
__global__ void k_chanstat(const float* __restrict__ x,
                           const float* __restrict__ masks) {
    int idx = blockIdx.x * blockDim.x + threadIdx.x;   // over NB*HW/2
    if (idx >= NB*(HW/2)) return;
    int b   = idx / (HW/2);
    int hw2 = idx - b * (HW/2);
    int p0  = 2*hw2;
    int r   = p0 / HD;
    int q0  = p0 - r*HD;

    const float2* xp = (const float2*)x + (size_t)b * NC * (HW/2) + hw2;
    float sx = 0.f, sy = 0.f;
    float mxx = -3.4e38f, mxy = -3.4e38f;
#pragma unroll 16
    for (int c = 0; c < NC; c++) {
        float2 v = __ldg(xp + (size_t)c * (HW/2));
        sx += v.x; sy += v.y;
        mxx = fmaxf(mxx, v.x);
        mxy = fmaxf(mxy, v.y);
    }

    const float* mp = masks + (size_t)b * HM * HM;
    float m0 = resize_m(mp, r, q0);
    float m1 = resize_m(mp, r, q0 + 1);

    ((float2*)g_m)[idx]    = make_float2(m0, m1);
    ((float2*)g_avg)[idx]  = make_float2(m0 * (sx * (1.f/NC)), m1 * (sy * (1.f/NC)));
    ((float2*)g_maxp)[idx] = make_float2(m0 * mxx, m1 * mxy);
}

// ---------------------------------------------------------------------------
// Kernel C: 7x7 conv over [avg, max, m] (zero pad 3) -> sigmoid -> s = m*atten.
// 16x16 output tile per block, 22x22x3 smem halo tile.
// ---------------------------------------------------------------------------
__global__ void k_conv(const float* __restrict__ cw) {
    __shared__ float sh[3][22][22];
    __shared__ float wsm[3*49];
    int t = threadIdx.x;                 // 256 threads
    int bx = blockIdx.x & 7;
    int by = (blockIdx.x >> 3) & 7;
    int b  = blockIdx.x >> 6;
    int h0 = by*16 - 3, w0 = bx*16 - 3;
    if (t < 147) wsm[t] = cw[t];
    for (int i = t; i < 22*22; i += 256) {
        int ih = i / 22, iw = i % 22;
        int hh = h0 + ih, ww = w0 + iw;
        bool ok = (hh >= 0) && (hh < HD) && (ww >= 0) && (ww < HD);
        if (ok) {
            int g = b*HW + hh*HD + ww;
            sh[0][ih][iw] = g_avg[g];
            sh[1][ih][iw] = g_maxp[g];
            sh[2][ih][iw] = g_m[g];
        } else {
            sh[0][ih][iw] = 0.f;
            sh[1][ih][iw] = 0.f;
            sh[2][ih][iw] = 0.f;
        }
    }
    __syncthreads();
    int ty = t >> 4, tx = t & 15;
    float acc = 0.f;
#pragma unroll
    for (int c = 0; c < 3; c++)
#pragma unroll
        for (int kh = 0; kh < 7; kh++)
#pragma unroll
            for (int kw = 0; kw < 7; kw++)
                acc += sh[c][ty+kh][tx+kw] * wsm[c*49 + kh*7 + kw];
    float at = 1.f / (1.f + expf(-acc));
    int h = h0 + 3 + ty, w = w0 + 3 + tx;
    int g = b*HW + h*HD + w;
    g_s[g] = g_m[g] * at;
}

// ---------------------------------------------------------------------------
// Kernel D: per (b,c): out = relu(5 * IN(x*s)). Two-pass: phase 1 streams x,s
// for sum/sumsq; phase 2 re-reads the same 64KB channel (L2-resident between
// phases). out is written with evict-first (__stcs) so it doesn't pollute L2.
// ---------------------------------------------------------------------------
__global__ void __launch_bounds__(512, 2)
k_norm(const float* __restrict__ x,
       const float* __restrict__ gamma,
       const float* __restrict__ beta,
       float* __restrict__ out) {
    int bc = blockIdx.x;
    int b = bc >> 8, c = bc & 255;
    const float4* xp = (const float4*)(x + (size_t)bc * HW);
    const float4* sp = (const float4*)(g_s + (size_t)b * HW);
    float4* op = (float4*)(out + (size_t)bc * HW);

    float sum = 0.f, ss = 0.f;
#pragma unroll
    for (int it = 0; it < 8; it++) {
        int i = it*512 + threadIdx.x;
        float4 xv = xp[i], sv = sp[i];
        float vx = xv.x*sv.x, vy = xv.y*sv.y, vz = xv.z*sv.z, vw = xv.w*sv.w;
        sum += (vx + vy) + (vz + vw);
        ss  += vx*vx + vy*vy + vz*vz + vw*vw;
    }
    // block reduction: warp shfl then 16 partials
    for (int o = 16; o > 0; o >>= 1) {
        sum += __shfl_down_sync(0xffffffffu, sum, o);
        ss  += __shfl_down_sync(0xffffffffu, ss,  o);
    }
    __shared__ float rs[16], rq[16];
    __shared__ float s_g, s_b;
    int wid = threadIdx.x >> 5, lid = threadIdx.x & 31;
    if (lid == 0) { rs[wid] = sum; rq[wid] = ss; }
    __syncthreads();
    if (threadIdx.x == 0) {
        float S = 0.f, Q = 0.f;
#pragma unroll
        for (int i = 0; i < 16; i++) { S += rs[i]; Q += rq[i]; }
        float mu  = S * (1.f/HW);
        float var = Q * (1.f/HW) - mu*mu;
        float inv = rsqrtf(var + 1e-5f);
        float gg  = gamma[c] * inv;
        s_g = 5.f * gg;
        s_b = 5.f * (beta[c] - mu * gg);
    }
    __syncthreads();
    float gg = s_g, bb = s_b;
#pragma unroll
    for (int it = 0; it < 8; it++) {
        int i = it*512 + threadIdx.x;
        float4 xv = xp[i], sv = sp[i];   // L2 hit (same 64KB read in phase 1)
        float4 ov = make_float4(fmaxf(0.f, xv.x*sv.x*gg + bb),
                                fmaxf(0.f, xv.y*sv.y*gg + bb),
                                fmaxf(0.f, xv.z*sv.z*gg + bb),
                                fmaxf(0.f, xv.w*sv.w*gg + bb));
        __stcs(op + i, ov);              // evict-first: don't pollute L2
    }
}

extern "C" void kernel_launch(void* const* d_in, const int* in_sizes, int n_in,
                              void* d_out, int out_size) {
    const float* x     = (const float*)d_in[0];
    const float* masks = (const float*)d_in[1];
    const float* cw    = (const float*)d_in[2];
    const float* gamma = (const float*)d_in[3];
    const float* beta  = (const float*)d_in[4];
    float* out = (float*)d_out;

    k_chanstat<<<(NB*(HW/2) + 127)/128, 128>>>(x, masks);
    k_conv    <<<NB*64, 256>>>(cw);
    k_norm    <<<NB*NC, 512>>>(x, gamma, beta, out);
}

// round 4
// speedup vs baseline: 1.0646x; 1.0646x over previous
#include <cuda_runtime.h>
#include <math.h>

#define NB 8
#define NC 256
#define HD 128
#define HW (HD*HD)
#define HM 512

// scratch (allocation-free rule: __device__ globals)
__device__ __align__(16) float g_m[NB*HW];     // resized mask
__device__ __align__(16) float g_avg[NB*HW];   // m * mean_c(x)
__device__ __align__(16) float g_maxp[NB*HW];  // m * max_c(x)
__device__ __align__(16) float g_s[NB*HW];     // m * sigmoid(conv)

// ---------------------------------------------------------------------------
// Kernel A: antialiased bilinear downsample 512x512 -> 128x128 (half-pixel).
// 8-tap triangle kernel {1,3,5,7,7,5,3,1}/8 per dim, renormalized at edges.
// ---------------------------------------------------------------------------
__global__ void k_resize(const float* __restrict__ masks) {
    int idx = blockIdx.x * blockDim.x + threadIdx.x;
    if (idx >= NB*HW) return;
    int b = idx / HW;
    int r = (idx / HD) % HD;
    int q = idx % HD;
    const float raw[8] = {0.125f,0.375f,0.625f,0.875f,0.875f,0.625f,0.375f,0.125f};
    float wr[8], wc[8]; int jr[8], jc[8];
    float tr = 0.f, tc = 0.f;
#pragma unroll
    for (int k = 0; k < 8; k++) {
        int j = 4*r - 2 + k;
        bool ok = (j >= 0) && (j < HM);
        wr[k] = ok ? raw[k] : 0.f;
        jr[k] = ok ? j : 0;
        tr += wr[k];
        j = 4*q - 2 + k;
        ok = (j >= 0) && (j < HM);
        wc[k] = ok ? raw[k] : 0.f;
        jc[k] = ok ? j : 0;
        tc += wc[k];
    }
    const float* mp = masks + (size_t)b * HM * HM;
    float acc = 0.f;
#pragma unroll
    for (int a = 0; a < 8; a++) {
        float rowacc = 0.f;
#pragma unroll
        for (int bb = 0; bb < 8; bb++)
            rowacc += wc[bb] * __ldg(mp + jr[a]*HM + jc[bb]);
        acc += wr[a] * rowacc;
    }
    g_m[idx] = acc / (tr * tc);
}

// ---------------------------------------------------------------------------
// Kernel B: channel mean/max, 4-way channel split for parallelism.
// Block = 256 threads = 64 pixels x 4 channel-groups (64 ch each).
// Coalesced 256B rows per group; smem tree-combine across groups.
// ---------------------------------------------------------------------------
__global__ void __launch_bounds__(256)
k_chanstat(const float* __restrict__ x) {
    __shared__ float s_sum[4][64];
    __shared__ float s_max[4][64];
    int pix = threadIdx.x & 63;
    int cg  = threadIdx.x >> 6;          // 0..3
    int p0  = blockIdx.x * 64;           // block never straddles a batch
    int b   = p0 / HW;
    int hw  = p0 - b * HW + pix;

    const float* xp = x + ((size_t)(b*NC + cg*64)) * HW + hw;
    float s = 0.f, mx = -3.4e38f;
#pragma unroll 16
    for (int c = 0; c < 64; c++) {
        float v = __ldg(xp + (size_t)c * HW);
        s += v;
        mx = fmaxf(mx, v);
    }
    s_sum[cg][pix] = s;
    s_max[cg][pix] = mx;
    __syncthreads();
    if (cg == 0) {
        float S  = s_sum[0][pix] + s_sum[1][pix] + s_sum[2][pix] + s_sum[3][pix];
        float M  = fmaxf(fmaxf(s_max[0][pix], s_max[1][pix]),
                         fmaxf(s_max[2][pix], s_max[3][pix]));
        int g = p0 + pix;
        float m = g_m[g];
        g_avg[g]  = m * (S * (1.f/NC));
        g_maxp[g] = m * M;
    }
}

// ---------------------------------------------------------------------------
// Kernel C: 7x7 conv over [avg, max, m] (zero pad 3) -> sigmoid -> s = m*atten.
// 16x16 output tile per block, 22x22x3 smem halo tile.
// ---------------------------------------------------------------------------
__global__ void k_conv(const float* __restrict__ cw) {
    __shared__ float sh[3][22][22];
    __shared__ float wsm[3*49];
    int t = threadIdx.x;                 // 256 threads
    int bx = blockIdx.x & 7;
    int by = (blockIdx.x >> 3) & 7;
    int b  = blockIdx.x >> 6;
    int h0 = by*16 - 3, w0 = bx*16 - 3;
    if (t < 147) wsm[t] = cw[t];
    for (int i = t; i < 22*22; i += 256) {
        int ih = i / 22, iw = i % 22;
        int hh = h0 + ih, ww = w0 + iw;
        bool ok = (hh >= 0) && (hh < HD) && (ww >= 0) && (ww < HD);
        if (ok) {
            int g = b*HW + hh*HD + ww;
            sh[0][ih][iw] = g_avg[g];
            sh[1][ih][iw] = g_maxp[g];
            sh[2][ih][iw] = g_m[g];
        } else {
            sh[0][ih][iw] = 0.f;
            sh[1][ih][iw] = 0.f;
            sh[2][ih][iw] = 0.f;
        }
    }
    __syncthreads();
    int ty = t >> 4, tx = t & 15;
    float acc = 0.f;
#pragma unroll
    for (int c = 0; c < 3; c++)
#pragma unroll
        for (int kh = 0; kh < 7; kh++)
#pragma unroll
            for (int kw = 0; kw < 7; kw++)
                acc += sh[c][ty+kh][tx+kw] * wsm[c*49 + kh*7 + kw];
    float at = 1.f / (1.f + expf(-acc));
    int h = h0 + 3 + ty, w = w0 + 3 + tx;
    int g = b*HW + h*HD + w;
    g_s[g] = g_m[g] * at;
}

// ---------------------------------------------------------------------------
// Kernel D: per (b,c): out = relu(5 * IN(x*s)). Two-pass: phase 1 streams x,s
// for sum/sumsq; phase 2 re-reads the same 64KB channel (L2-resident between
// phases). out is written with evict-first (__stcs) so it doesn't pollute L2.
// ---------------------------------------------------------------------------
__global__ void k_norm(const float* __restrict__ x,
                       const float* __restrict__ gamma,
                       const float* __restrict__ beta,
                       float* __restrict__ out) {
    int bc = blockIdx.x;
    int b = bc >> 8, c = bc & 255;
    const float4* xp = (const float4*)(x + (size_t)bc * HW);
    const float4* sp = (const float4*)(g_s + (size_t)b * HW);
    float4* op = (float4*)(out + (size_t)bc * HW);

    float sum = 0.f, ss = 0.f;
#pragma unroll
    for (int it = 0; it < 8; it++) {
        int i = it*512 + threadIdx.x;
        float4 xv = xp[i], sv = sp[i];
        float vx = xv.x*sv.x, vy = xv.y*sv.y, vz = xv.z*sv.z, vw = xv.w*sv.w;
        sum += (vx + vy) + (vz + vw);
        ss  += vx*vx + vy*vy + vz*vz + vw*vw;
    }
    // block reduction: warp shfl then 16 partials
    for (int o = 16; o > 0; o >>= 1) {
        sum += __shfl_down_sync(0xffffffffu, sum, o);
        ss  += __shfl_down_sync(0xffffffffu, ss,  o);
    }
    __shared__ float rs[16], rq[16];
    __shared__ float s_g, s_b;
    int wid = threadIdx.x >> 5, lid = threadIdx.x & 31;
    if (lid == 0) { rs[wid] = sum; rq[wid] = ss; }
    __syncthreads();
    if (threadIdx.x == 0) {
        float S = 0.f, Q = 0.f;
#pragma unroll
        for (int i = 0; i < 16; i++) { S += rs[i]; Q += rq[i]; }
        float mu  = S * (1.f/HW);
        float var = Q * (1.f/HW) - mu*mu;
        float inv = rsqrtf(var + 1e-5f);
        float gg  = gamma[c] * inv;
        s_g = 5.f * gg;
        s_b = 5.f * (beta[c] - mu * gg);
    }
    __syncthreads();
    float gg = s_g, bb = s_b;
#pragma unroll
    for (int it = 0; it < 8; it++) {
        int i = it*512 + threadIdx.x;
        float4 xv = xp[i], sv = sp[i];   // L2 hit (same 64KB read in phase 1)
        float4 ov = make_float4(fmaxf(0.f, xv.x*sv.x*gg + bb),
                                fmaxf(0.f, xv.y*sv.y*gg + bb),
                                fmaxf(0.f, xv.z*sv.z*gg + bb),
                                fmaxf(0.f, xv.w*sv.w*gg + bb));
        __stcs(op + i, ov);              // evict-first: don't pollute L2
    }
}

extern "C" void kernel_launch(void* const* d_in, const int* in_sizes, int n_in,
                              void* d_out, int out_size) {
    const float* x     = (const float*)d_in[0];
    const float* masks = (const float*)d_in[1];
    const float* cw    = (const float*)d_in[2];
    const float* gamma = (const float*)d_in[3];
    const float* beta  = (const float*)d_in[4];
    float* out = (float*)d_out;

    k_resize  <<<(NB*HW + 255)/256, 256>>>(masks);
    k_chanstat<<<NB*HW/64, 256>>>(x);
    k_conv    <<<NB*64, 256>>>(cw);
    k_norm    <<<NB*NC, 512>>>(x, gamma, beta, out);
}

// round 5
// speedup vs baseline: 1.1473x; 1.0776x over previous
#include <cuda_runtime.h>
#include <math.h>

#define NB 8
#define NC 256
#define HD 128
#define HW (HD*HD)
#define HM 512

// scratch (allocation-free rule: __device__ globals)
__device__ __align__(16) float g_m[NB*HW];     // resized mask
__device__ __align__(16) float g_avg[NB*HW];   // m * mean_c(x)
__device__ __align__(16) float g_maxp[NB*HW];  // m * max_c(x)
__device__ __align__(16) float g_s[NB*HW];     // m * sigmoid(conv)

// ---------------------------------------------------------------------------
// Kernel A: antialiased bilinear downsample 512x512 -> 128x128 (half-pixel).
// 8-tap triangle kernel {1,3,5,7,7,5,3,1}/8 per dim, renormalized at edges.
// ---------------------------------------------------------------------------
__global__ void k_resize(const float* __restrict__ masks) {
    int idx = blockIdx.x * blockDim.x + threadIdx.x;
    if (idx >= NB*HW) return;
    int b = idx / HW;
    int r = (idx / HD) % HD;
    int q = idx % HD;
    const float raw[8] = {0.125f,0.375f,0.625f,0.875f,0.875f,0.625f,0.375f,0.125f};
    float wr[8], wc[8]; int jr[8], jc[8];
    float tr = 0.f, tc = 0.f;
#pragma unroll
    for (int k = 0; k < 8; k++) {
        int j = 4*r - 2 + k;
        bool ok = (j >= 0) && (j < HM);
        wr[k] = ok ? raw[k] : 0.f;
        jr[k] = ok ? j : 0;
        tr += wr[k];
        j = 4*q - 2 + k;
        ok = (j >= 0) && (j < HM);
        wc[k] = ok ? raw[k] : 0.f;
        jc[k] = ok ? j : 0;
        tc += wc[k];
    }
    const float* mp = masks + (size_t)b * HM * HM;
    float acc = 0.f;
#pragma unroll
    for (int a = 0; a < 8; a++) {
        float rowacc = 0.f;
#pragma unroll
        for (int bb = 0; bb < 8; bb++)
            rowacc += wc[bb] * __ldg(mp + jr[a]*HM + jc[bb]);
        acc += wr[a] * rowacc;
    }
    g_m[idx] = acc / (tr * tc);
}

// ---------------------------------------------------------------------------
// Kernel B: channel mean/max, 4-way channel split for parallelism.
// Block = 256 threads = 64 pixels x 4 channel-groups (64 ch each).
// Traverses batches 0->7 in time; leaves the TAIL batches hot in L2.
// ---------------------------------------------------------------------------
__global__ void __launch_bounds__(256)
k_chanstat(const float* __restrict__ x) {
    __shared__ float s_sum[4][64];
    __shared__ float s_max[4][64];
    int pix = threadIdx.x & 63;
    int cg  = threadIdx.x >> 6;          // 0..3
    int p0  = blockIdx.x * 64;           // block never straddles a batch
    int b   = p0 / HW;
    int hw  = p0 - b * HW + pix;

    const float* xp = x + ((size_t)(b*NC + cg*64)) * HW + hw;
    float s = 0.f, mx = -3.4e38f;
#pragma unroll 16
    for (int c = 0; c < 64; c++) {
        float v = __ldg(xp + (size_t)c * HW);
        s += v;
        mx = fmaxf(mx, v);
    }
    s_sum[cg][pix] = s;
    s_max[cg][pix] = mx;
    __syncthreads();
    if (cg == 0) {
        float S  = s_sum[0][pix] + s_sum[1][pix] + s_sum[2][pix] + s_sum[3][pix];
        float M  = fmaxf(fmaxf(s_max[0][pix], s_max[1][pix]),
                         fmaxf(s_max[2][pix], s_max[3][pix]));
        int g = p0 + pix;
        float m = g_m[g];
        g_avg[g]  = m * (S * (1.f/NC));
        g_maxp[g] = m * M;
    }
}

// ---------------------------------------------------------------------------
// Kernel C: 7x7 conv over [avg, max, m] (zero pad 3) -> sigmoid -> s = m*atten.
// 16x16 output tile per block, 22x22x3 smem halo tile.
// ---------------------------------------------------------------------------
__global__ void k_conv(const float* __restrict__ cw) {
    __shared__ float sh[3][22][22];
    __shared__ float wsm[3*49];
    int t = threadIdx.x;                 // 256 threads
    int bx = blockIdx.x & 7;
    int by = (blockIdx.x >> 3) & 7;
    int b  = blockIdx.x >> 6;
    int h0 = by*16 - 3, w0 = bx*16 - 3;
    if (t < 147) wsm[t] = cw[t];
    for (int i = t; i < 22*22; i += 256) {
        int ih = i / 22, iw = i % 22;
        int hh = h0 + ih, ww = w0 + iw;
        bool ok = (hh >= 0) && (hh < HD) && (ww >= 0) && (ww < HD);
        if (ok) {
            int g = b*HW + hh*HD + ww;
            sh[0][ih][iw] = g_avg[g];
            sh[1][ih][iw] = g_maxp[g];
            sh[2][ih][iw] = g_m[g];
        } else {
            sh[0][ih][iw] = 0.f;
            sh[1][ih][iw] = 0.f;
            sh[2][ih][iw] = 0.f;
        }
    }
    __syncthreads();
    int ty = t >> 4, tx = t & 15;
    float acc = 0.f;
#pragma unroll
    for (int c = 0; c < 3; c++)
#pragma unroll
        for (int kh = 0; kh < 7; kh++)
#pragma unroll
            for (int kw = 0; kw < 7; kw++)
                acc += sh[c][ty+kh][tx+kw] * wsm[c*49 + kh*7 + kw];
    float at = 1.f / (1.f + expf(-acc));
    int h = h0 + 3 + ty, w = w0 + 3 + tx;
    int g = b*HW + h*HD + w;
    g_s[g] = g_m[g] * at;
}

// ---------------------------------------------------------------------------
// Kernel D: per (b,c): out = relu(5 * IN(x*s)). Two-pass with L2 reuse.
// REVERSE batch order: chanstat finishes with the tail batches of x hot in
// L2, so the first k_norm wave (bc high = batch 7,6,...) reads x from L2
// instead of DRAM. Phase 2 re-reads the same 64KB channel (L2-resident).
// out written evict-first (__stcs) to not pollute L2.
// ---------------------------------------------------------------------------
__global__ void k_norm(const float* __restrict__ x,
                       const float* __restrict__ gamma,
                       const float* __restrict__ beta,
                       float* __restrict__ out) {
    int bc = (NB*NC - 1) - blockIdx.x;   // batch 7 first (L2-hot from chanstat)
    int b = bc >> 8, c = bc & 255;
    const float4* xp = (const float4*)(x + (size_t)bc * HW);
    const float4* sp = (const float4*)(g_s + (size_t)b * HW);
    float4* op = (float4*)(out + (size_t)bc * HW);

    float sum = 0.f, ss = 0.f;
#pragma unroll
    for (int it = 0; it < 8; it++) {
        int i = it*512 + threadIdx.x;
        float4 xv = xp[i], sv = sp[i];
        float vx = xv.x*sv.x, vy = xv.y*sv.y, vz = xv.z*sv.z, vw = xv.w*sv.w;
        sum += (vx + vy) + (vz + vw);
        ss  += vx*vx + vy*vy + vz*vz + vw*vw;
    }
    // block reduction: warp shfl then 16 partials
    for (int o = 16; o > 0; o >>= 1) {
        sum += __shfl_down_sync(0xffffffffu, sum, o);
        ss  += __shfl_down_sync(0xffffffffu, ss,  o);
    }
    __shared__ float rs[16], rq[16];
    __shared__ float s_g, s_b;
    int wid = threadIdx.x >> 5, lid = threadIdx.x & 31;
    if (lid == 0) { rs[wid] = sum; rq[wid] = ss; }
    __syncthreads();
    if (threadIdx.x == 0) {
        float S = 0.f, Q = 0.f;
#pragma unroll
        for (int i = 0; i < 16; i++) { S += rs[i]; Q += rq[i]; }
        float mu  = S * (1.f/HW);
        float var = Q * (1.f/HW) - mu*mu;
        float inv = rsqrtf(var + 1e-5f);
        float gg  = gamma[c] * inv;
        s_g = 5.f * gg;
        s_b = 5.f * (beta[c] - mu * gg);
    }
    __syncthreads();
    float gg = s_g, bb = s_b;
#pragma unroll
    for (int it = 0; it < 8; it++) {
        int i = it*512 + threadIdx.x;
        float4 xv = xp[i], sv = sp[i];   // L2 hit (same 64KB read in phase 1)
        float4 ov = make_float4(fmaxf(0.f, xv.x*sv.x*gg + bb),
                                fmaxf(0.f, xv.y*sv.y*gg + bb),
                                fmaxf(0.f, xv.z*sv.z*gg + bb),
                                fmaxf(0.f, xv.w*sv.w*gg + bb));
        __stcs(op + i, ov);              // evict-first: don't pollute L2
    }
}

extern "C" void kernel_launch(void* const* d_in, const int* in_sizes, int n_in,
                              void* d_out, int out_size) {
    const float* x     = (const float*)d_in[0];
    const float* masks = (const float*)d_in[1];
    const float* cw    = (const float*)d_in[2];
    const float* gamma = (const float*)d_in[3];
    const float* beta  = (const float*)d_in[4];
    float* out = (float*)d_out;

    k_resize  <<<(NB*HW + 255)/256, 256>>>(masks);
    k_chanstat<<<NB*HW/64, 256>>>(x);
    k_conv    <<<NB*64, 256>>>(cw);
    k_norm    <<<NB*NC, 512>>>(x, gamma, beta, out);
}